// round 6
// baseline (speedup 1.0000x reference)
#include <cuda_runtime.h>
#include <cuda_fp16.h>
#include <math.h>

#define STATE 4096
#define CDIM  1024
#define FANIN 5121
#define NB    148          // persistent blocks, all resident (1/SM)
#define BT    1024
#define NWC   28           // output columns owned per block (148*28 = 4144 >= 4096)
#define SMC   27           // W1 columns cached in dynamic smem
#define PREPR 32           // row-chunks in c@W precompute
#define DSMEM (SMC * STATE * 2 + 32 * NWC * 4)

// ---------------- device scratch ----------------
__device__ __half g_WT1[(size_t)STATE * STATE];   // W1[1024:5120][:]^T col-major
__device__ __half g_WT2[(size_t)STATE * STATE];
__device__ float  g_cwp1[PREPR * STATE];          // c@W1 row-chunk partials
__device__ float  g_cwp2[PREPR * STATE];
__device__ float  g_wt1[STATE], g_wt2[STATE];     // t-row weights
__device__ float  g_x0[STATE];                    // sigmoid(yst)
__device__ float  g_x1[STATE];                    // s1
__device__ float  g_x2[STATE];                    // s0'*f
__device__ float  g_x3[STATE];                    // s1'*da1
__device__ float  g_rp[NB];                       // per-block sum(zdd^2) partials
__device__ unsigned g_flag[NB * 32];              // barrier flags, 128B apart

__device__ __forceinline__ float sigm(float x) { return 1.0f / (1.0f + expf(-x)); }

// ---------------- distributed flag barrier (release/acquire) -----------------
__device__ __forceinline__ void gsync(int b, int tid, unsigned step) {
    __syncthreads();
    if (tid == 0)
        asm volatile("st.release.gpu.u32 [%0], %1;"
                     :: "l"(&g_flag[b * 32]), "r"(step) : "memory");
    if (tid < NB) {
        unsigned v;
        do {
            asm volatile("ld.acquire.gpu.u32 %0, [%1];"
                         : "=r"(v) : "l"(&g_flag[tid * 32]) : "memory");
        } while (v < step);
    }
    __syncthreads();
}

// ---------------- parallel c@W precompute (32-row chunks, 512 blocks) --------
__global__ void k_prep(const float* __restrict__ W1, const float* __restrict__ W2,
                       const float* __restrict__ c,  const float* __restrict__ h) {
    __shared__ float cs[32];
    const int j  = blockIdx.x * 256 + threadIdx.x;
    const int r0 = blockIdx.y * 32;
    if (threadIdx.x < 32) cs[threadIdx.x] = __ldg(c + r0 + threadIdx.x);
    __syncthreads();
    float a1 = 0.0f, a2 = 0.0f;
    #pragma unroll
    for (int i = 0; i < 32; i++) {
        float ci = cs[i];
        a1 = fmaf(ci, __ldg(W1 + (size_t)(r0 + i) * STATE + j), a1);
        a2 = fmaf(ci, __ldg(W2 + (size_t)(r0 + i) * STATE + j), a2);
    }
    g_cwp1[blockIdx.y * STATE + j] = a1;
    g_cwp2[blockIdx.y * STATE + j] = a2;
    if (blockIdx.y == 0) {
        g_wt1[j] = __ldg(W1 + (size_t)(FANIN - 1) * STATE + j);
        g_wt2[j] = __ldg(W2 + (size_t)(FANIN - 1) * STATE + j);
        g_x0[j]  = sigm(__ldg(h + j));
        if (blockIdx.x == 0 && threadIdx.x < NB) g_flag[threadIdx.x * 32] = 0u;
    }
}

// ---------------- transpose state-rows of W to fp16 col-major ----------------
__global__ void k_transpose(const float* __restrict__ W1, const float* __restrict__ W2) {
    __shared__ float tile[32][33];
    const float* __restrict__ W = blockIdx.z ? W2 : W1;
    __half* __restrict__ WT = blockIdx.z ? g_WT2 : g_WT1;
    const int jt = blockIdx.x * 32, rt = blockIdx.y * 32;
    const int tx = threadIdx.x, ty = threadIdx.y;
    #pragma unroll
    for (int k = 0; k < 32; k += 8)
        tile[ty + k][tx] = W[(size_t)(CDIM + rt + ty + k) * STATE + (jt + tx)];
    __syncthreads();
    #pragma unroll
    for (int k = 0; k < 32; k += 8)
        WT[(size_t)(jt + ty + k) * STATE + (rt + tx)] = __float2half_rn(tile[tx][ty + k]);
}

// ---------------- row-sliced dot: warp w covers rows [128w,128w+128) ---------
// Results: red[w*NWC + col] = partial dot of this warp's row slice, all 28 cols.
__device__ __forceinline__ void dot28(const float* __restrict__ xin,
                                      const __half* __restrict__ gW,
                                      const __half* __restrict__ sW,
                                      int vsm, int e0, int w, int l,
                                      float* __restrict__ red) {
    const int roff = w * 128 + l * 4;                 // 4 rows per lane
    const float4 xv = __ldcg(reinterpret_cast<const float4*>(xin + roff));
    #pragma unroll
    for (int bat = 0; bat < 2; bat++) {
        float acc[14];
        #pragma unroll
        for (int j = 0; j < 14; j++) {
            const int lc = bat * 14 + j;
            const __half* col = (lc < vsm)
                ? sW + (size_t)lc * STATE
                : gW + (size_t)(((e0 + lc) < STATE) ? (e0 + lc) : 0) * STATE;
            const uint2 wv = *reinterpret_cast<const uint2*>(col + roff);
            const float2 f0 = __half22float2(*reinterpret_cast<const __half2*>(&wv.x));
            const float2 f1 = __half22float2(*reinterpret_cast<const __half2*>(&wv.y));
            acc[j] = fmaf(xv.x, f0.x, fmaf(xv.y, f0.y, fmaf(xv.z, f1.x, xv.w * f1.y)));
        }
        #pragma unroll
        for (int j = 0; j < 14; j++) {
            float v = acc[j];
            #pragma unroll
            for (int o = 16; o; o >>= 1) v += __shfl_down_sync(0xffffffffu, v, o);
            if (l == 0) red[w * NWC + bat * 14 + j] = v;
        }
    }
}

// ---------------- persistent ODE kernel (single RK4 step) --------------------
__global__ void __launch_bounds__(BT, 1)
k_ode(const float* __restrict__ h, const float* __restrict__ tptr,
      const float* __restrict__ b1, const float* __restrict__ b2,
      float* __restrict__ out) {
    extern __shared__ __align__(16) unsigned char sm_raw[];
    __half* sW1 = reinterpret_cast<__half*>(sm_raw);
    float*  red = reinterpret_cast<float*>(sm_raw + (size_t)SMC * STATE * 2);

    const int b = blockIdx.x, tid = threadIdx.x;
    const int w = tid >> 5, l = tid & 31;
    const int e0 = b * NWC;
    int vc = STATE - e0; vc = vc < 0 ? 0 : (vc > NWC ? NWC : vc);
    const int vsm = vc < SMC ? vc : SMC;

    // fill W1 smem tile (cols e0..e0+vsm-1, contiguous in col-major g_WT1)
    {
        const uint4* src = reinterpret_cast<const uint4*>(g_WT1 + (size_t)e0 * STATE);
        uint4* dst = reinterpret_cast<uint4*>(sW1);
        const int n = vsm * (STATE / 8);
        for (int i = tid; i < n; i += BT) dst[i] = src[i];
    }

    const float tval = __ldg(tptr);
    const float hs = tval;                           // single step: h = t

    // warp-0 lane-c per-column RK state
    const int e = e0 + l;
    const bool own = (w == 0) && (l < vc);
    float cw1 = 0.f, cw2 = 0.f, wt1 = 0.f, wt2 = 0.f;
    float ycur = 0.f, kacc = 0.f, s0p = 0.f, s1p = 0.f, f = 0.f;
    if (own) {
        cw1 = __ldg(b1 + e); cw2 = __ldg(b2 + e);
        #pragma unroll 8
        for (int p = 0; p < PREPR; p++) {
            cw1 += __ldcg(g_cwp1 + p * STATE + e);
            cw2 += __ldcg(g_cwp2 + p * STATE + e);
        }
        wt1 = g_wt1[e]; wt2 = g_wt2[e];
        ycur = __ldg(h + e);
        float s0 = sigm(ycur);
        s0p = s0 * (1.0f - s0);
    }
    float racc = 0.f;                                 // warp 31, lane 0
    __syncthreads();
    unsigned step = 0;

    #pragma unroll 1
    for (int s = 0; s < 4; s++) {
        const float cst = (s == 0) ? 0.0f : (s == 3) ? 1.0f : 0.5f;
        const float tau = hs * cst;

        // warp 31: r bookkeeping for previous stage (g_rp valid since last gsync)
        if (s > 0 && w == 31) {
            float ss = 0.f;
            for (int i = l; i < NB; i += 32) ss += __ldcg(g_rp + i);
            #pragma unroll
            for (int o = 16; o; o >>= 1) ss += __shfl_down_sync(0xffffffffu, ss, o);
            if (l == 0) {
                float kr = ss * (1.0f / (float)STATE);
                racc += (s == 1) ? kr : 2.0f * kr;
            }
        }

        // ===== phase 0: a1 = x0@W1 (+cw1+tau*wt1); s1 =====
        dot28(g_x0, g_WT1, sW1, vsm, e0, w, l, red);
        __syncthreads();
        if (own) {
            float d = 0.f;
            #pragma unroll
            for (int ww = 0; ww < 32; ww++) d += red[ww * NWC + l];
            float s1 = sigm(d + cw1 + tau * wt1);
            s1p = s1 * (1.0f - s1);
            __stcg(g_x1 + e, s1);
        }
        gsync(b, tid, ++step);

        // ===== phase 1: f = x1@W2 (+cw2+tau*wt2); x2 = s0p*f =====
        dot28(g_x1, g_WT2, sW1, 0, e0, w, l, red);
        __syncthreads();
        if (own) {
            float d = 0.f;
            #pragma unroll
            for (int ww = 0; ww < 32; ww++) d += red[ww * NWC + l];
            f = d + cw2 + tau * wt2;
            __stcg(g_x2 + e, s0p * f);
        }
        gsync(b, tid, ++step);

        // ===== phase 2: da1 = x2@W1 + wt1; x3 = s1p*da1 =====
        dot28(g_x2, g_WT1, sW1, vsm, e0, w, l, red);
        __syncthreads();
        if (own) {
            float d = 0.f;
            #pragma unroll
            for (int ww = 0; ww < 32; ww++) d += red[ww * NWC + l];
            __stcg(g_x3 + e, s1p * (d + wt1));
        }
        gsync(b, tid, ++step);

        // ===== phase 3: zdd = x3@W2 + wt2; fused RK update =====
        dot28(g_x3, g_WT2, sW1, 0, e0, w, l, red);
        __syncthreads();
        if (w == 0) {
            float sq = 0.f;
            if (own) {
                float d = 0.f;
                #pragma unroll
                for (int ww = 0; ww < 32; ww++) d += red[ww * NWC + l];
                float zdd = d + wt2;
                sq = zdd * zdd;
                float kv = f, yst;
                if (s == 0)      { kacc = kv;          yst = ycur + 0.5f * hs * kv; }
                else if (s == 1) { kacc += 2.0f * kv;  yst = ycur + 0.5f * hs * kv; }
                else if (s == 2) { kacc += 2.0f * kv;  yst = ycur + hs * kv; }
                else { ycur += (hs / 6.0f) * (kacc + kv); yst = ycur; }
                float s0 = sigm(yst);
                s0p = s0 * (1.0f - s0);
                __stcg(g_x0 + e, s0);
            }
            #pragma unroll
            for (int o = 16; o; o >>= 1) sq += __shfl_down_sync(0xffffffffu, sq, o);
            if (l == 0) __stcg(g_rp + b, sq);
        }
        gsync(b, tid, ++step);
    }

    // final r (k4) + outputs
    if (b == 0 && w == 31) {
        float ss = 0.f;
        for (int i = l; i < NB; i += 32) ss += __ldcg(g_rp + i);
        #pragma unroll
        for (int o = 16; o; o >>= 1) ss += __shfl_down_sync(0xffffffffu, ss, o);
        if (l == 0) {
            float kr = ss * (1.0f / (float)STATE);
            out[STATE] = (hs / 6.0f) * (racc + kr);
        }
    }
    if (own) out[e] = ycur;
}

// ---------------- launch ------------------------------------------------------
extern "C" void kernel_launch(void* const* d_in, const int* in_sizes, int n_in,
                              void* d_out, int out_size) {
    const float *h = nullptr, *t = nullptr, *c = nullptr;
    const float *W1 = nullptr, *b1 = nullptr, *W2 = nullptr, *b2 = nullptr;
    for (int i = 0; i < n_in; i++) {
        const float* p = (const float*)d_in[i];
        int sz = in_sizes[i];
        if (sz == 1) t = p;
        else if (sz == CDIM) c = p;
        else if (sz == FANIN * STATE) { if (!W1) W1 = p; else W2 = p; }
        else if (sz == STATE) { if (!h) h = p; else if (!b1) b1 = p; else b2 = p; }
    }

    cudaFuncSetAttribute(k_ode, cudaFuncAttributeMaxDynamicSharedMemorySize, DSMEM);

    k_prep<<<dim3(16, PREPR), 256>>>(W1, W2, c, h);
    k_transpose<<<dim3(128, 128, 2), dim3(32, 8)>>>(W1, W2);
    k_ode<<<NB, BT, DSMEM>>>(h, t, b1, b2, (float*)d_out);
}

// round 10
// speedup vs baseline: 1.4870x; 1.4870x over previous
#include <cuda_runtime.h>
#include <cuda_fp16.h>
#include <math.h>

#define STATE 4096
#define CDIM  1024
#define FANIN 5121
#define NB    148
#define BT    1024
#define NWC   28
#define PREPR 32
#define NTRB  (128*128*2)
#define NPRB  (16*PREPR)

// ---------------- device scratch ----------------
__device__ __half g_WT1[(size_t)STATE * STATE];   // W1[1024:5120][:]^T col-major fp16
__device__ __half g_WT2[(size_t)STATE * STATE];
__device__ float  g_cwp1[PREPR * STATE], g_cwp2[PREPR * STATE];
__device__ float  g_wt1[STATE], g_wt2[STATE];     // t-row weights
__device__ __half g_x0h[STATE];                   // sigmoid(yst)
__device__ __half g_x1h[STATE];                   // s1
__device__ __half g_x2h[STATE];                   // s0'*f
__device__ __half g_x3h[STATE];                   // s1'*da1
__device__ float  g_rp[NB];
__device__ unsigned g_flag[NB * 32];

__device__ __forceinline__ float sigm(float x) { return 1.0f / (1.0f + expf(-x)); }
__device__ __forceinline__ void sth(__half* p, float v) {
    unsigned short u = __half_as_ushort(__float2half_rn(v));
    asm volatile("st.global.cg.u16 [%0], %1;" :: "l"(p), "h"(u) : "memory");
}

// ---------------- distributed flag barrier (release/acquire) -----------------
__device__ __forceinline__ void gsync(int b, int tid, unsigned step) {
    __syncthreads();
    if (tid == 0)
        asm volatile("st.release.gpu.u32 [%0], %1;"
                     :: "l"(&g_flag[b * 32]), "r"(step) : "memory");
    if (tid < NB) {
        unsigned v;
        do {
            asm volatile("ld.acquire.gpu.u32 %0, [%1];"
                         : "=r"(v) : "l"(&g_flag[tid * 32]) : "memory");
        } while (v < step);
    }
    __syncthreads();
}

// ---------------- fused transpose + c@W precompute ----------------------------
__global__ void k_pre(const float* __restrict__ W1, const float* __restrict__ W2,
                      const float* __restrict__ c,  const float* __restrict__ h) {
    const int bb = blockIdx.x, tid = threadIdx.x;
    if (bb < NTRB) {
        __shared__ float tile[32][33];
        const int z = bb >> 14;            // 128*128 = 16384 tiles per matrix
        const int rem = bb & 16383;
        const int bx = rem & 127, by = rem >> 7;
        const float* __restrict__ W = z ? W2 : W1;
        __half* __restrict__ WT = z ? g_WT2 : g_WT1;
        const int jt = bx * 32, rt = by * 32;
        const int tx = tid & 31, ty = tid >> 5;     // ty 0..7
        #pragma unroll
        for (int k = 0; k < 32; k += 8)
            tile[ty + k][tx] = W[(size_t)(CDIM + rt + ty + k) * STATE + (jt + tx)];
        __syncthreads();
        #pragma unroll
        for (int k = 0; k < 32; k += 8)
            WT[(size_t)(jt + ty + k) * STATE + (rt + tx)] = __float2half_rn(tile[tx][ty + k]);
    } else {
        __shared__ float cs[32];
        const int pb = bb - NTRB;
        const int px = pb & 15, py = pb >> 4;
        const int j = px * 256 + tid;
        const int r0 = py * 32;
        if (tid < 32) cs[tid] = __ldg(c + r0 + tid);
        __syncthreads();
        float a1 = 0.f, a2 = 0.f;
        #pragma unroll
        for (int i = 0; i < 32; i++) {
            float ci = cs[i];
            a1 = fmaf(ci, __ldg(W1 + (size_t)(r0 + i) * STATE + j), a1);
            a2 = fmaf(ci, __ldg(W2 + (size_t)(r0 + i) * STATE + j), a2);
        }
        g_cwp1[py * STATE + j] = a1;
        g_cwp2[py * STATE + j] = a2;
        if (py == 0) {
            g_wt1[j] = __ldg(W1 + (size_t)(FANIN - 1) * STATE + j);
            g_wt2[j] = __ldg(W2 + (size_t)(FANIN - 1) * STATE + j);
            g_x0h[j] = __float2half_rn(sigm(__ldg(h + j)));
            if (px == 0 && tid < NB) g_flag[tid * 32] = 0u;
        }
    }
}

// ---------------- paired column dot: one weight load feeds two dots ----------
template <bool DOB>
__device__ __forceinline__ void dotpair(const __half* __restrict__ Wc,
                                        const __half* __restrict__ xa,
                                        const __half* __restrict__ xb,
                                        int l, float& ra, float& rb) {
    const uint4* __restrict__ wp = reinterpret_cast<const uint4*>(Wc) + l;
    const uint4* __restrict__ pa = reinterpret_cast<const uint4*>(xa) + l;
    const uint4* __restrict__ pb = reinterpret_cast<const uint4*>(xb) + l;
    float a0 = 0.f, a1 = 0.f, a2 = 0.f, a3 = 0.f;
    float c0 = 0.f, c1 = 0.f, c2 = 0.f, c3 = 0.f;
    #pragma unroll
    for (int i = 0; i < 16; i++) {
        const uint4 wv = wp[i * 32];
        const float2 w0 = __half22float2(*reinterpret_cast<const __half2*>(&wv.x));
        const float2 w1 = __half22float2(*reinterpret_cast<const __half2*>(&wv.y));
        const float2 w2 = __half22float2(*reinterpret_cast<const __half2*>(&wv.z));
        const float2 w3 = __half22float2(*reinterpret_cast<const __half2*>(&wv.w));
        {
            const uint4 va = pa[i * 32];
            const float2 f0 = __half22float2(*reinterpret_cast<const __half2*>(&va.x));
            const float2 f1 = __half22float2(*reinterpret_cast<const __half2*>(&va.y));
            const float2 f2 = __half22float2(*reinterpret_cast<const __half2*>(&va.z));
            const float2 f3 = __half22float2(*reinterpret_cast<const __half2*>(&va.w));
            a0 = fmaf(w0.x, f0.x, a0); a1 = fmaf(w0.y, f0.y, a1);
            a2 = fmaf(w1.x, f1.x, a2); a3 = fmaf(w1.y, f1.y, a3);
            a0 = fmaf(w2.x, f2.x, a0); a1 = fmaf(w2.y, f2.y, a1);
            a2 = fmaf(w3.x, f3.x, a2); a3 = fmaf(w3.y, f3.y, a3);
        }
        if (DOB) {
            const uint4 vb = pb[i * 32];
            const float2 f0 = __half22float2(*reinterpret_cast<const __half2*>(&vb.x));
            const float2 f1 = __half22float2(*reinterpret_cast<const __half2*>(&vb.y));
            const float2 f2 = __half22float2(*reinterpret_cast<const __half2*>(&vb.z));
            const float2 f3 = __half22float2(*reinterpret_cast<const __half2*>(&vb.w));
            c0 = fmaf(w0.x, f0.x, c0); c1 = fmaf(w0.y, f0.y, c1);
            c2 = fmaf(w1.x, f1.x, c2); c3 = fmaf(w1.y, f1.y, c3);
            c0 = fmaf(w2.x, f2.x, c0); c1 = fmaf(w2.y, f2.y, c1);
            c2 = fmaf(w3.x, f3.x, c2); c3 = fmaf(w3.y, f3.y, c3);
        }
    }
    ra = (a0 + a1) + (a2 + a3);
    rb = DOB ? (c0 + c1) + (c2 + c3) : 0.f;
    #pragma unroll
    for (int o = 16; o; o >>= 1) {
        ra += __shfl_down_sync(0xffffffffu, ra, o);
        if (DOB) rb += __shfl_down_sync(0xffffffffu, rb, o);
    }
}

// ---------------- persistent ODE kernel (RK4, 1 step, pipelined JVP) ---------
__global__ void __launch_bounds__(BT, 1)
k_ode(const float* __restrict__ h, const float* __restrict__ tptr,
      const float* __restrict__ b1, const float* __restrict__ b2,
      float* __restrict__ out) {
    __shared__ __align__(16) __half sxa[STATE];
    __shared__ __align__(16) __half sxb[STATE];
    __shared__ float zz[NWC];

    const int b = blockIdx.x, tid = threadIdx.x;
    const int w = tid >> 5, l = tid & 31;
    const int e0 = b * NWC;
    int vc = STATE - e0; vc = vc < 0 ? 0 : (vc > NWC ? NWC : vc);
    const int e = e0 + (w < NWC ? w : 0);
    const int ce = e < STATE ? e : STATE - 1;
    const bool own = (w < vc);
    const __half* __restrict__ c1 = g_WT1 + (size_t)ce * STATE;
    const __half* __restrict__ c2 = g_WT2 + (size_t)ce * STATE;

    const float hs = __ldg(tptr);

    // owner state (lane 0 of warps 0..vc-1, one output column each)
    float cw1 = 0.f, cw2 = 0.f, wt1 = 0.f, wt2 = 0.f;
    float y0 = 0.f, yst = 0.f, kacc = 0.f, s0p = 0.f, s1p_prev = 0.f, ycur = 0.f;
    if (own && l == 0) {
        cw1 = __ldg(b1 + e); cw2 = __ldg(b2 + e);
        #pragma unroll 8
        for (int p = 0; p < PREPR; p++) {
            cw1 += __ldcg(g_cwp1 + p * STATE + e);
            cw2 += __ldcg(g_cwp2 + p * STATE + e);
        }
        wt1 = g_wt1[e]; wt2 = g_wt2[e];
        y0 = __ldg(h + e);
        float s0 = sigm(y0);
        s0p = s0 * (1.0f - s0);
    }
    float racc = 0.f;                 // block 0, warp 31, lane 0
    unsigned step = 0;

    #pragma unroll 1
    for (int s = 0; s < 4; s++) {
        const float tau = hs * ((s == 0) ? 0.f : (s == 3) ? 1.f : 0.5f);

        // ===== A phase: fwd a1(stage s) on W1  [+ jvp da1(stage s-1) on W1] =====
        if (tid < 512) ((uint4*)sxa)[tid] = __ldcg(((const uint4*)g_x0h) + tid);
        else           ((uint4*)sxb)[tid - 512] = __ldcg(((const uint4*)g_x2h) + (tid - 512));
        __syncthreads();
        if (b == 0 && w == 31 && s >= 2) {     // r-sum for stage s-2 (rp from prev B)
            float ss = 0.f;
            for (int i = l; i < NB; i += 32) ss += __ldcg(g_rp + i);
            #pragma unroll
            for (int o = 16; o; o >>= 1) ss += __shfl_down_sync(0xffffffffu, ss, o);
            if (l == 0) racc += (s == 2 ? 1.f : 2.f) * ss;
        }
        if (w < NWC) {
            float ra, rb;
            dotpair<true>(c1, sxa, sxb, l, ra, rb);
            if (own && l == 0) {
                float s1 = sigm(ra + cw1 + tau * wt1);
                sth(g_x1h + e, s1);
                if (s >= 1) sth(g_x3h + e, s1p_prev * (rb + wt1));
                s1p_prev = s1 * (1.f - s1);
            }
        }
        gsync(b, tid, ++step);

        // ===== B phase: fwd f(stage s) on W2  [+ jvp zdd(stage s-1) on W2] =====
        if (tid < 512) ((uint4*)sxa)[tid] = __ldcg(((const uint4*)g_x1h) + tid);
        else           ((uint4*)sxb)[tid - 512] = __ldcg(((const uint4*)g_x3h) + (tid - 512));
        __syncthreads();
        float sq = 0.f;
        if (w < NWC) {
            float ra, rb;
            dotpair<true>(c2, sxa, sxb, l, ra, rb);
            if (own && l == 0) {
                float f = ra + cw2 + tau * wt2;
                sth(g_x2h + e, s0p * f);             // x2[s] uses sigma'(yst[s])
                if (s == 0)      { kacc = f;          yst = y0 + 0.5f * hs * f; }
                else if (s == 1) { kacc += 2.f * f;   yst = y0 + 0.5f * hs * f; }
                else if (s == 2) { kacc += 2.f * f;   yst = y0 + hs * f; }
                else             { ycur = y0 + (hs / 6.f) * (kacc + f); }
                if (s < 3) {
                    float s0 = sigm(yst);
                    s0p = s0 * (1.f - s0);
                    sth(g_x0h + e, s0);
                }
                if (s >= 1) { float zdd = rb + wt2; sq = zdd * zdd; }
            }
        }
        if (l == 0 && w < NWC) zz[w] = sq;
        __syncthreads();
        if (s >= 1 && w == 28) {
            float v = (l < NWC) ? zz[l] : 0.f;
            #pragma unroll
            for (int o = 16; o; o >>= 1) v += __shfl_down_sync(0xffffffffu, v, o);
            if (l == 0) __stcg(g_rp + b, v);         // sum(zdd^2) for stage s-1
        }
        gsync(b, tid, ++step);
    }

    // ===== P8: jvp stage-3 A (W1) =====
    if (tid < 512) ((uint4*)sxa)[tid] = __ldcg(((const uint4*)g_x2h) + tid);
    __syncthreads();
    if (b == 0 && w == 31) {                          // r-sum stage 2
        float ss = 0.f;
        for (int i = l; i < NB; i += 32) ss += __ldcg(g_rp + i);
        #pragma unroll
        for (int o = 16; o; o >>= 1) ss += __shfl_down_sync(0xffffffffu, ss, o);
        if (l == 0) racc += 2.f * ss;
    }
    if (w < NWC) {
        float ra, rb;
        dotpair<false>(c1, sxa, sxa, l, ra, rb);
        if (own && l == 0) sth(g_x3h + e, s1p_prev * (ra + wt1));
    }
    gsync(b, tid, ++step);

    // ===== P9: jvp stage-3 B (W2) =====
    if (tid < 512) ((uint4*)sxa)[tid] = __ldcg(((const uint4*)g_x3h) + tid);
    __syncthreads();
    {
        float sq = 0.f;
        if (w < NWC) {
            float ra, rb;
            dotpair<false>(c2, sxa, sxa, l, ra, rb);
            if (own && l == 0) { float zdd = ra + wt2; sq = zdd * zdd; }
        }
        if (l == 0 && w < NWC) zz[w] = sq;
        __syncthreads();
        if (w == 28) {
            float v = (l < NWC) ? zz[l] : 0.f;
            #pragma unroll
            for (int o = 16; o; o >>= 1) v += __shfl_down_sync(0xffffffffu, v, o);
            if (l == 0) __stcg(g_rp + b, v);          // stage 3
        }
    }
    gsync(b, tid, ++step);

    // final r (stage 3, weight 1) + outputs
    if (b == 0 && w == 31) {
        float ss = 0.f;
        for (int i = l; i < NB; i += 32) ss += __ldcg(g_rp + i);
        #pragma unroll
        for (int o = 16; o; o >>= 1) ss += __shfl_down_sync(0xffffffffu, ss, o);
        if (l == 0) {
            racc += ss;
            out[STATE] = (hs / 6.f) * racc * (1.f / (float)STATE);
        }
    }
    if (own && l == 0) out[e] = ycur;
}

// ---------------- launch ------------------------------------------------------
extern "C" void kernel_launch(void* const* d_in, const int* in_sizes, int n_in,
                              void* d_out, int out_size) {
    const float *h = nullptr, *t = nullptr, *c = nullptr;
    const float *W1 = nullptr, *b1 = nullptr, *W2 = nullptr, *b2 = nullptr;
    for (int i = 0; i < n_in; i++) {
        const float* p = (const float*)d_in[i];
        int sz = in_sizes[i];
        if (sz == 1) t = p;
        else if (sz == CDIM) c = p;
        else if (sz == FANIN * STATE) { if (!W1) W1 = p; else W2 = p; }
        else if (sz == STATE) { if (!h) h = p; else if (!b1) b1 = p; else b2 = p; }
    }

    k_pre<<<NTRB + NPRB, 256>>>(W1, W2, c, h);
    k_ode<<<NB, BT>>>(h, t, b1, b2, (float*)d_out);
}